// round 3
// baseline (speedup 1.0000x reference)
#include <cuda_runtime.h>
#include <cuda_bf16.h>
#include <cstdint>

#define BATCH 512
#define SEQ   2048
#define TAGS  32
#define START_IDX 30
#define STOP_IDX  31
#define FULLM 0xffffffffu
#define LN2F  0.6931471805599453f

// per-batch (logZ - score); reduced by the last block of the same kernel
__device__ float    g_val[BATCH];
__device__ unsigned g_ticket = 0;

static __device__ __forceinline__ __nv_bfloat162 asb(unsigned u) {
    __nv_bfloat162 v; *reinterpret_cast<unsigned*>(&v) = u; return v;
}
static __device__ __forceinline__ unsigned asu(__nv_bfloat162 v) {
    return *reinterpret_cast<unsigned*>(&v);
}

// ---------------------------------------------------------------------------
// Fused forward + score for TWO chains per warp, packed in bf16x2.
// Lane j holds (qA_j, qB_j). One SHFL broadcasts both chains' alpha;
// __hfma2 against row2[j] = (expT[i][j], expT[i][j]) computes both matvecs.
// Renorm by lane-0's value every 4 steps (reuses the j=0 broadcast -> free).
// Score path stays exact fp32. Last block reduces all 512 values.
// ---------------------------------------------------------------------------
__global__ void __launch_bounds__(64, 1)
crf_kernel(const float* __restrict__ feats, const float* __restrict__ trans,
           const int* __restrict__ tags, float* __restrict__ out)
{
    __shared__ float st[TAGS * TAGS];   // exact transitions (score path)
    __shared__ float xw[2];
    __shared__ int   isLast;

    const int tid  = threadIdx.x;
    const int w    = tid >> 5;
    const int lane = tid & 31;
    const int warpId = blockIdx.x * 2 + w;     // 0..255
    const int cA = warpId * 2, cB = cA + 1;    // two chains per warp

    for (int i = tid; i < TAGS * TAGS; i += 64) st[i] = trans[i];
    __syncthreads();

    // row2[j] = (exp(T[lane][j]), exp(T[lane][j])); exp(-1e4) == 0 blocks rows.
    __nv_bfloat162 row2[TAGS];
#pragma unroll
    for (int j = 0; j < TAGS; j++)
        row2[j] = __float2bfloat162_rn(__expf(trans[lane * TAGS + j]));
    const __nv_bfloat162 stop2 =
        __float2bfloat162_rn(__expf(trans[STOP_IDX * TAGS + lane]));

    const int* tgA = tags + (size_t)cA * SEQ;
    const int* tgB = tags + (size_t)cB * SEQ;
    const size_t baseA = (size_t)cA * SEQ * TAGS + lane;
    const size_t baseB = (size_t)cB * SEQ * TAGS + lane;

    // feats prefetch rings, distance 8
    float fbA[8], fbB[8];
#pragma unroll
    for (int k = 0; k < 8; k++) {
        fbA[k] = feats[baseA + (size_t)k * TAGS];
        fbB[k] = feats[baseB + (size_t)k * TAGS];
    }

    // q init: indicator at START for both chains
    unsigned qb = asu(__float2bfloat162_rn(lane == START_IDX ? 1.0f : 0.0f));
    float ClA = 0.f, ClB = 0.f;     // accumulated log2 normalizers (uniform)
    float scA = 0.f, scB = 0.f;     // gold-score partials (per-lane)
    int prevA = START_IDX, prevB = START_IDX;
    int4 t4A, t4B;                  // 4 steps of gold tags

    auto step = [&](int s, int u) __attribute__((always_inline)) {
        const int ph = u & 3;
        const float fA = fbA[u], fB = fbB[u];
        const int sp = s + 8;
        if (sp < SEQ) {
            fbA[u] = feats[baseA + (size_t)sp * TAGS];
            fbB[u] = feats[baseB + (size_t)sp * TAGS];
        }
        if (ph == 0) {   // vectorized tag fetch for 4 steps (16B aligned)
            t4A = *(const int4*)(tgA + s);
            t4B = *(const int4*)(tgB + s);
        }
        const int tA = (ph == 0) ? t4A.x : (ph == 1) ? t4A.y : (ph == 2) ? t4A.z : t4A.w;
        const int tB = (ph == 0) ? t4B.x : (ph == 1) ? t4B.y : (ph == 2) ? t4B.z : t4B.w;

        const float EFA = __expf(fA);
        const float EFB = __expf(fB);

        // broadcast + dual matvec: 32 SHFL + 4 HMUL2 + 28 HFMA2
        const unsigned r0 = __shfl_sync(FULLM, qb, 0);
        const unsigned r1 = __shfl_sync(FULLM, qb, 1);
        const unsigned r2 = __shfl_sync(FULLM, qb, 2);
        const unsigned r3 = __shfl_sync(FULLM, qb, 3);
        __nv_bfloat162 acc0 = __hmul2(asb(r0), row2[0]);
        __nv_bfloat162 acc1 = __hmul2(asb(r1), row2[1]);
        __nv_bfloat162 acc2 = __hmul2(asb(r2), row2[2]);
        __nv_bfloat162 acc3 = __hmul2(asb(r3), row2[3]);
#pragma unroll
        for (int j = 4; j < TAGS; j += 4) {
            const unsigned x0 = __shfl_sync(FULLM, qb, j + 0);
            const unsigned x1 = __shfl_sync(FULLM, qb, j + 1);
            const unsigned x2 = __shfl_sync(FULLM, qb, j + 2);
            const unsigned x3 = __shfl_sync(FULLM, qb, j + 3);
            acc0 = __hfma2(asb(x0), row2[j + 0], acc0);
            acc1 = __hfma2(asb(x1), row2[j + 1], acc1);
            acc2 = __hfma2(asb(x2), row2[j + 2], acc2);
            acc3 = __hfma2(asb(x3), row2[j + 3], acc3);
        }

        // multiplier: exp(feat), with renorm by lane-0 value every 4th step
        float mA, mB;
        if (ph == 3) {
            const float q0A = __bfloat162float(asb(r0).x);
            const float q0B = __bfloat162float(asb(r0).y);
            mA = __fdividef(EFA, q0A);
            mB = __fdividef(EFB, q0B);
            ClA += __log2f(q0A);
            ClB += __log2f(q0B);
        } else {
            mA = EFA; mB = EFB;
        }
        __nv_bfloat162 ef2;
        ef2.x = __float2bfloat16(mA);
        ef2.y = __float2bfloat16(mB);

        const __nv_bfloat162 sum2 =
            __hadd2(__hadd2(acc0, acc1), __hadd2(acc2, acc3));
        qb = asu(__hmul2(sum2, ef2));

        // gold-path score (exact fp32, off critical path)
        if (lane == tA) scA += fA + st[tA * TAGS + prevA];
        prevA = tA;
        if (lane == tB) scB += fB + st[tB * TAGS + prevB];
        prevB = tB;
    };

    // prologue steps 0..7 (compile-time ring indices)
#pragma unroll
    for (int s = 0; s < 8; s++) step(s, s);
    // steps 8..2047
    for (int s0 = 8; s0 < SEQ; s0 += 8) {
#pragma unroll
        for (int u = 0; u < 8; u++) step(s0 + u, u);
    }

    // terminal: logZ = C*ln2 + ln(sum_i q_i * exp(T[STOP][i]))
    unsigned vb = asu(__hmul2(asb(qb), stop2));
#pragma unroll
    for (int o = 16; o; o >>= 1) {
        const unsigned ov = __shfl_xor_sync(FULLM, vb, o);
        vb = asu(__hadd2(asb(vb), asb(ov)));
        scA += __shfl_xor_sync(FULLM, scA, o);
        scB += __shfl_xor_sync(FULLM, scB, o);
    }
    if (lane == 0) {
        const float vA = __bfloat162float(asb(vb).x);
        const float vB = __bfloat162float(asb(vb).y);
        const float logZA = (ClA + __log2f(vA)) * LN2F;
        const float logZB = (ClB + __log2f(vB)) * LN2F;
        g_val[cA] = logZA - (scA + st[STOP_IDX * TAGS + prevA]);
        g_val[cB] = logZB - (scB + st[STOP_IDX * TAGS + prevB]);
    }

    // ---- last block performs the deterministic final reduction ----
    __syncthreads();
    __threadfence();
    if (tid == 0) {
        const unsigned t = atomicAdd(&g_ticket, 1);
        isLast = (t == gridDim.x - 1);
    }
    __syncthreads();
    if (isLast) {
        __threadfence();
        if (tid == 0) g_ticket = 0;   // reset for next graph replay
        float s = 0.f;
        for (int i = tid; i < BATCH; i += 64) s += g_val[i];
#pragma unroll
        for (int o = 16; o; o >>= 1) s += __shfl_xor_sync(FULLM, s, o);
        if (lane == 0) xw[w] = s;
        __syncthreads();
        if (tid == 0) out[0] = xw[0] + xw[1];
    }
}

// ---------------------------------------------------------------------------
extern "C" void kernel_launch(void* const* d_in, const int* in_sizes, int n_in,
                              void* d_out, int out_size)
{
    (void)in_sizes; (void)n_in; (void)out_size;
    const float* feats = (const float*)d_in[0];   // [512, 2048, 32] f32
    const float* trans = (const float*)d_in[1];   // [32, 32] f32
    const int*   tags  = (const int*)d_in[2];     // [512, 2048] i32
    float* out = (float*)d_out;                   // scalar f32

    // 128 blocks x 2 warps x 2 chains = 512 chains; single launch
    crf_kernel<<<128, 64>>>(feats, trans, tags, out);
}

// round 5
// speedup vs baseline: 2.6936x; 2.6936x over previous
#include <cuda_runtime.h>
#include <cuda_bf16.h>
#include <cstdint>

#define BATCH 512
#define SEQ   2048
#define TAGS  32
#define START_IDX 30
#define STOP_IDX  31
#define FULLM 0xffffffffu
#define LN2F  0.6931471805599453f

__device__ float    g_logZ[BATCH];
__device__ float    g_sc[BATCH];
__device__ unsigned g_ticket = 0;

// ---- packed fp32x2 helpers (PTX-only ops; ptxas won't fuse these itself) ----
static __device__ __forceinline__ unsigned long long pack2(float lo, float hi) {
    unsigned long long d;
    asm("mov.b64 %0, {%1, %2};" : "=l"(d) : "r"(__float_as_uint(lo)), "r"(__float_as_uint(hi)));
    return d;
}
static __device__ __forceinline__ void unpack2(unsigned long long v, float& lo, float& hi) {
    unsigned a, b;
    asm("mov.b64 {%0, %1}, %2;" : "=r"(a), "=r"(b) : "l"(v));
    lo = __uint_as_float(a); hi = __uint_as_float(b);
}
static __device__ __forceinline__ unsigned long long fma2(unsigned long long a, unsigned long long b, unsigned long long c) {
    unsigned long long d;
    asm("fma.rn.f32x2 %0, %1, %2, %3;" : "=l"(d) : "l"(a), "l"(b), "l"(c));
    return d;
}
static __device__ __forceinline__ unsigned long long mul2(unsigned long long a, unsigned long long b) {
    unsigned long long d;
    asm("mul.rn.f32x2 %0, %1, %2;" : "=l"(d) : "l"(a), "l"(b));
    return d;
}
static __device__ __forceinline__ unsigned long long add2(unsigned long long a, unsigned long long b) {
    unsigned long long d;
    asm("add.rn.f32x2 %0, %1, %2;" : "=l"(d) : "l"(a), "l"(b));
    return d;
}

// ---------------------------------------------------------------------------
// Single launch, role-split by blockIdx:
//   blocks [0,128)   : forward algorithm, 4 warps = 4 chains each
//   blocks [128,256) : gold-path score, 4 warps = 4 chains each
//   last-arriving block: deterministic final reduction
// All 256 blocks are co-resident in one wave (launch_bounds occ=2).
// ---------------------------------------------------------------------------
__global__ void __launch_bounds__(128, 2)
crf_all(const float* __restrict__ feats, const float* __restrict__ trans,
        const int* __restrict__ tags, float* __restrict__ out)
{
    __shared__ float st[TAGS * TAGS];
    __shared__ __align__(16) float bc[4][2][TAGS];  // [warp][parity][32]
    __shared__ float red[4];
    __shared__ int   isLast;

    const int tid  = threadIdx.x;
    const int w    = tid >> 5;
    const int lane = tid & 31;

    for (int i = tid; i < TAGS * TAGS; i += 128) st[i] = trans[i];
    __syncthreads();

    if (blockIdx.x < 128) {
        // =================== FORWARD ROLE ===================
        const int chain = blockIdx.x * 4 + w;

        // packed rows of exp(transitions): row2[k] = (E[lane][2k], E[lane][2k+1])
        unsigned long long row2[TAGS / 2];
#pragma unroll
        for (int k = 0; k < TAGS / 2; k++)
            row2[k] = pack2(__expf(st[lane * TAGS + 2 * k]),
                            __expf(st[lane * TAGS + 2 * k + 1]));
        const float eStart  = __expf(st[lane * TAGS + START_IDX]);
        const float expStop = __expf(st[STOP_IDX * TAGS + lane]);

        const size_t base = (size_t)chain * SEQ * TAGS + lane;
        float* const b0 = bc[w][0];
        float* const b1 = bc[w][1];

        float fb[8];
#pragma unroll
        for (int k = 0; k < 8; k++) fb[k] = __ldg(feats + base + (size_t)k * TAGS);

        // step 0: alpha is the indicator at START
        float p  = __expf(fb[0]) * eStart;
        float Cl = 0.0f;
        fb[0] = __ldg(feats + base + (size_t)8 * TAGS);

        auto step = [&](int s, int u, float* wb) __attribute__((always_inline)) {
            const float f = fb[u];
            const int sp = s + 8;
            if (sp < SEQ) fb[u] = __ldg(feats + base + (size_t)sp * TAGS);
            const float EF = __expf(f);

            wb[lane] = p;                       // STS broadcast source
            __syncwarp(FULLM);
            const ulonglong2* qv = (const ulonglong2*)wb;  // 8x LDS.128
            const ulonglong2 v0 = qv[0], v1 = qv[1], v2 = qv[2], v3 = qv[3];
            const ulonglong2 v4 = qv[4], v5 = qv[5], v6 = qv[6], v7 = qv[7];

            // off-path: renorm multiplier (every 4th step, uses q0 = lo(v0.x))
            float m;
            if ((s & 3) == 3) {
                float q0, q1d; unpack2(v0.x, q0, q1d); (void)q1d;
                m = __fdividef(EF, q0);
                Cl += __log2f(q0);
            } else {
                m = EF;
            }

            // dual-lane packed matvec: 8 MUL2 + 8 FMA2, 8 accumulators
            unsigned long long a0 = mul2(v0.x, row2[0]);
            unsigned long long a1 = mul2(v0.y, row2[1]);
            unsigned long long a2 = mul2(v1.x, row2[2]);
            unsigned long long a3 = mul2(v1.y, row2[3]);
            unsigned long long a4 = mul2(v2.x, row2[4]);
            unsigned long long a5 = mul2(v2.y, row2[5]);
            unsigned long long a6 = mul2(v3.x, row2[6]);
            unsigned long long a7 = mul2(v3.y, row2[7]);
            a0 = fma2(v4.x, row2[8],  a0);
            a1 = fma2(v4.y, row2[9],  a1);
            a2 = fma2(v5.x, row2[10], a2);
            a3 = fma2(v5.y, row2[11], a3);
            a4 = fma2(v6.x, row2[12], a4);
            a5 = fma2(v6.y, row2[13], a5);
            a6 = fma2(v7.x, row2[14], a6);
            a7 = fma2(v7.y, row2[15], a7);

            const unsigned long long t0 = add2(add2(a0, a1), add2(a2, a3));
            const unsigned long long t1 = add2(add2(a4, a5), add2(a6, a7));
            const unsigned long long tt = add2(t0, t1);
            float lo, hi; unpack2(tt, lo, hi);
            p = (lo + hi) * m;
        };

        // steps 1..7 (prologue; compile-time ring indices)
#pragma unroll
        for (int s = 1; s < 8; s++) step(s, s, (s & 1) ? b1 : b0);
        // steps 8..2047 (255 blocks of 8)
        for (int s0 = 8; s0 < SEQ; s0 += 8) {
#pragma unroll
            for (int u = 0; u < 8; u++) step(s0 + u, u, (u & 1) ? b1 : b0);
        }

        float v = p * expStop;
#pragma unroll
        for (int o = 16; o; o >>= 1) v += __shfl_xor_sync(FULLM, v, o);
        if (lane == 0)
            g_logZ[chain] = (Cl + __log2f(v)) * LN2F;

    } else {
        // =================== SCORE ROLE ===================
        const int chain = (blockIdx.x - 128) * 4 + w;
        const int* tg = tags + (size_t)chain * SEQ;
        const size_t fbase = (size_t)chain * SEQ * TAGS;

        float sum = 0.0f;
        for (int s = lane; s < SEQ; s += 32) {
            const int t  = __ldg(tg + s);
            const int tp = (s == 0) ? START_IDX : __ldg(tg + s - 1);
            sum += st[t * TAGS + tp] + __ldg(feats + fbase + (size_t)s * TAGS + t);
        }
#pragma unroll
        for (int o = 16; o; o >>= 1) sum += __shfl_xor_sync(FULLM, sum, o);
        if (lane == 0)
            g_sc[chain] = sum + st[STOP_IDX * TAGS + __ldg(tg + SEQ - 1)];
    }

    // =================== LAST-BLOCK REDUCTION ===================
    __syncthreads();
    __threadfence();
    if (tid == 0) {
        const unsigned t = atomicAdd(&g_ticket, 1);
        isLast = (t == 255);
    }
    __syncthreads();
    if (isLast) {
        __threadfence();
        if (tid == 0) g_ticket = 0;   // reset for next graph replay
        float s = 0.0f;
        for (int i = tid; i < BATCH; i += 128) s += g_logZ[i] - g_sc[i];
#pragma unroll
        for (int o = 16; o; o >>= 1) s += __shfl_xor_sync(FULLM, s, o);
        if (lane == 0) red[w] = s;
        __syncthreads();
        if (tid == 0) out[0] = ((red[0] + red[1]) + (red[2] + red[3]));
    }
}

// ---------------------------------------------------------------------------
extern "C" void kernel_launch(void* const* d_in, const int* in_sizes, int n_in,
                              void* d_out, int out_size)
{
    (void)in_sizes; (void)n_in; (void)out_size;
    const float* feats = (const float*)d_in[0];   // [512, 2048, 32] f32
    const float* trans = (const float*)d_in[1];   // [32, 32] f32
    const int*   tags  = (const int*)d_in[2];     // [512, 2048] i32
    float* out = (float*)d_out;                   // scalar f32

    crf_all<<<256, 128>>>(feats, trans, tags, out);
}